// round 6
// baseline (speedup 1.0000x reference)
#include <cuda_runtime.h>
#include <cstdint>

// PWC-Net correlation, B=8, C=128, H=112, W=192, 81 disps (dy,dx in [-4,4]).
// Round 5b (compile fix: ulonglong2): 4-pixel threads with LDG.128
// (3 loads cover the 12-col window, shared between the two pixel pairs)
// -> 1.5x fewer L1 wavefronts per pixel. Pad kernel is an aligned float4 copy.

#define B_ 8
#define C_ 128
#define H_ 112
#define W_ 192
#define HW_ (H_ * W_)
#define WP_ 200     // W + 8
#define HWP_ (H_ * WP_)

typedef unsigned long long ull;

// W-padded copy of `second`: [B, C, H, WP], 91.8 MB
__device__ __align__(16) float g_spad[B_ * C_ * HWP_];

__device__ __forceinline__ void fma2(ull& acc, ull a, ull b) {
    asm("fma.rn.f32x2 %0, %1, %2, %0;" : "+l"(acc) : "l"(a), "l"(b));
}
__device__ __forceinline__ void mul2(ull& v, ull s) {
    asm("mul.rn.f32x2 %0, %0, %1;" : "+l"(v) : "l"(s));
}
__device__ __forceinline__ ull pack_hl(ull a, ull b) {   // (a.hi, b.lo)
    return (a >> 32) | (b << 32);
}
__device__ __forceinline__ ull swap2(ull a) {            // (a.hi, a.lo)
    return (a >> 32) | (a << 32);
}

// one thread per padded float4: row = 50 float4; q=0 and q=49 are all-pad.
__global__ __launch_bounds__(256)
void pad_kernel(const float* __restrict__ second) {
    int i = blockIdx.x * blockDim.x + threadIdx.x;
    const int total = B_ * C_ * H_ * (WP_ / 4);
    if (i >= total) return;
    int q   = i % (WP_ / 4);             // 0..49
    int row = i / (WP_ / 4);             // bc*H + y
    float4 v = make_float4(0.f, 0.f, 0.f, 0.f);
    if (q >= 1 && q <= 48) {
        v = *reinterpret_cast<const float4*>(second + (size_t)row * W_ + (4 * q - 4));
    }
    reinterpret_cast<float4*>(g_spad)[i] = v;
}

__global__ __launch_bounds__(432, 2)
void corr81_kernel(const float* __restrict__ first,
                   float* __restrict__ out) {
    const int h   = blockIdx.x;        // 0..111
    const int b   = blockIdx.y;        // 0..7
    const int tid = threadIdx.x;       // 0..431
    const int pq  = tid % 48;          // pixel-quad index
    const int g   = tid / 48;          // dy index 0..8
    const int w0  = 4 * pq;            // pixels w0..w0+3

    // pair a = (w0, w0+1), pair b = (w0+2, w0+3)
    // e_*[m]: even dx=2m products; a_*[m]: swapped products for odd dx.
    ull ea[5], aa[5], eb[5], ab[5];
#pragma unroll
    for (int m = 0; m < 5; m++) { ea[m]=0; aa[m]=0; eb[m]=0; ab[m]=0; }

    const int y = h + g - 4;
    if (y >= 0 && y < H_) {
        const float4* srow = reinterpret_cast<const float4*>(
            g_spad + ((size_t)(b * C_) * H_ + y) * WP_ + w0);
        const float4* fptr = reinterpret_cast<const float4*>(
            first + ((size_t)(b * C_) * H_ + h) * W_ + w0);

        for (int c = 0; c < C_; c++) {
            const float4 F  = *fptr;  fptr += HW_ / 4;
            const float4 V0 = srow[0];
            const float4 V1 = srow[1];
            const float4 V2 = srow[2];
            srow += HWP_ / 4;

            const ull f2a = (ull)__float_as_uint(F.x) | ((ull)__float_as_uint(F.y) << 32);
            const ull f2b = (ull)__float_as_uint(F.z) | ((ull)__float_as_uint(F.w) << 32);
            const ull fsa = swap2(f2a);
            const ull fsb = swap2(f2b);

            const ull E0 = (ull)__float_as_uint(V0.x) | ((ull)__float_as_uint(V0.y) << 32);
            const ull E1 = (ull)__float_as_uint(V0.z) | ((ull)__float_as_uint(V0.w) << 32);
            const ull E2 = (ull)__float_as_uint(V1.x) | ((ull)__float_as_uint(V1.y) << 32);
            const ull E3 = (ull)__float_as_uint(V1.z) | ((ull)__float_as_uint(V1.w) << 32);
            const ull E4 = (ull)__float_as_uint(V2.x) | ((ull)__float_as_uint(V2.y) << 32);
            const ull E5 = (ull)__float_as_uint(V2.z) | ((ull)__float_as_uint(V2.w) << 32);

            fma2(ea[0], f2a, E0);  fma2(aa[0], fsa, E0);
            fma2(ea[1], f2a, E1);  fma2(aa[1], fsa, E1);
            fma2(ea[2], f2a, E2);  fma2(aa[2], fsa, E2);
            fma2(ea[3], f2a, E3);  fma2(aa[3], fsa, E3);
            fma2(ea[4], f2a, E4);  fma2(aa[4], fsa, E4);

            fma2(eb[0], f2b, E1);  fma2(ab[0], fsb, E1);
            fma2(eb[1], f2b, E2);  fma2(ab[1], fsb, E2);
            fma2(eb[2], f2b, E3);  fma2(ab[2], fsb, E3);
            fma2(eb[3], f2b, E4);  fma2(ab[3], fsb, E4);
            fma2(eb[4], f2b, E5);  fma2(ab[4], fsb, E5);
        }
    }

    const unsigned sb = __float_as_uint(1.0f / (float)C_);
    const ull scale2 = (ull)sb | ((ull)sb << 32);

    // channel d = g*9 + dx; store 16B (cols w0..w0+3), aligned
    float* od = out + (((size_t)(b * 81 + g * 9)) * H_ + h) * W_ + w0;
#pragma unroll
    for (int m = 0; m < 5; m++) {          // even dx = 2m
        ull va = ea[m]; mul2(va, scale2);
        ull vb = eb[m]; mul2(vb, scale2);
        ulonglong2 pk; pk.x = va; pk.y = vb;
        *reinterpret_cast<ulonglong2*>(od + (size_t)(2 * m) * HW_) = pk;
    }
#pragma unroll
    for (int m = 0; m < 4; m++) {          // odd dx = 2m+1
        ull va = pack_hl(aa[m], aa[m + 1]); mul2(va, scale2);
        ull vb = pack_hl(ab[m], ab[m + 1]); mul2(vb, scale2);
        ulonglong2 pk; pk.x = va; pk.y = vb;
        *reinterpret_cast<ulonglong2*>(od + (size_t)(2 * m + 1) * HW_) = pk;
    }
}

extern "C" void kernel_launch(void* const* d_in, const int* in_sizes, int n_in,
                              void* d_out, int out_size) {
    const float* first  = (const float*)d_in[0];
    const float* second = (const float*)d_in[1];
    float* out = (float*)d_out;

    const int pad_elems = B_ * C_ * H_ * (WP_ / 4);      // float4 count
    pad_kernel<<<(pad_elems + 255) / 256, 256>>>(second);

    dim3 grid(H_, B_);   // (112, 8)
    corr81_kernel<<<grid, 432>>>(first, out);
}